// round 9
// baseline (speedup 1.0000x reference)
#include <cuda_runtime.h>
#include <cstdint>

// Problem constants
#define B_  64
#define H_  128
#define W_  128
#define C_  10
#define FD_ 32
#define HID_ 64

// Tile config
#define TW 32
#define TH 8
#define HW 34   // halo width  (TW+2)
#define HH 10   // halo height (TH+2)
#define NPIX  (TW*TH)   // 256
#define NHALO (HW*HH)   // 340
#define NTHREADS 512
#define NWARP 16

// Hidden-dim "pos" layout: pos(j) = 2*(j&31) + (j>>5); j(pos) = (pos>>1) + (pos&1)*32
// y / hs / u arrays and per-j weights are stored in pos order: a warp lane owns
// the pair (j=lane, j=lane+32) as one 8-byte value at float-offset 2*lane.

// Shared memory layout (float offsets). Regions reused across phases:
//   SOUT aliases SY  (SY dead after phase C)
//   SAGG aliases SC  (SC dead after phase C)
//   SU   aliases SHS (SHS dead after phase D)
#define OFF_SY     0                          // NHALO*64 = 21760
#define OFF_SOUT   OFF_SY
#define OFF_SB     (OFF_SY + NHALO*HID_)      // 21760 ; rows stride 10
#define OFF_SC     (OFF_SB + NHALO*10)        // 25160 ; DUPLICATED: NPIX*48
#define OFF_SAGG   OFF_SC                     // NPIX*12 (after C)
#define OFF_SHS    (OFF_SC + NPIX*48)         // 37448 ; NPIX*64
#define OFF_SU     OFF_SHS
#define OFF_WSELF  (OFF_SHS + NPIX*HID_)      // 53832 ; pos-interleaved
#define OFF_WNEIGH (OFF_WSELF + 640)          // pos-interleaved
#define OFF_WC     (OFF_WNEIGH + 640)         // pos-interleaved
#define OFF_MW2T   (OFF_WC + 192)             // [k][pos]
#define OFF_UW2T   (OFF_MW2T + 640)           // [k][pos]
#define OFF_UW1    (OFF_UW2T + 640)           // pos-interleaved
#define OFF_UB1    (OFF_UW1 + 1280)           // pos-interleaved
#define OFF_BASE   (OFF_UB1 + 64)             // pos-interleaved
#define OFF_MB2    (OFF_BASE + 64)
#define OFF_UB2    (OFF_MB2 + 12)
#define OFF_GAMMA  (OFF_UB2 + 12)
#define OFF_BETA   (OFF_GAMMA + 12)
#define SMEM_FLOATS (OFF_BETA + 12)           // 58040
#define SMEM_BYTES  (SMEM_FLOATS * 4)         // 232160 (<= 232448 limit)

// ---- packed f32x2 helpers (sm_103a) ----
__device__ __forceinline__ uint64_t f2_pack(float lo, float hi) {
    uint64_t r; asm("mov.b64 %0, {%1, %2};" : "=l"(r) : "f"(lo), "f"(hi)); return r;
}
__device__ __forceinline__ void f2_unpack(uint64_t v, float& lo, float& hi) {
    asm("mov.b64 {%0, %1}, %2;" : "=f"(lo), "=f"(hi) : "l"(v));
}
__device__ __forceinline__ uint64_t f2_add(uint64_t a, uint64_t b) {
    uint64_t d; asm("add.rn.f32x2 %0, %1, %2;" : "=l"(d) : "l"(a), "l"(b)); return d;
}
__device__ __forceinline__ uint64_t f2_fma(uint64_t a, uint64_t b, uint64_t c) {
    uint64_t d; asm("fma.rn.f32x2 %0, %1, %2, %3;" : "=l"(d) : "l"(a), "l"(b), "l"(c)); return d;
}

__global__ void __launch_bounds__(NTHREADS, 1)
cmp_kernel(const float* __restrict__ beliefs,
           const float* __restrict__ constraints,
           const float* __restrict__ fnembed,
           const float* __restrict__ mw1, const float* __restrict__ mb1,
           const float* __restrict__ mw2, const float* __restrict__ mb2,
           const float* __restrict__ uw1, const float* __restrict__ ub1,
           const float* __restrict__ uw2, const float* __restrict__ ub2,
           const float* __restrict__ gamma_, const float* __restrict__ beta_,
           float* __restrict__ out)
{
    extern __shared__ __align__(16) float sm[];
    const int tid = threadIdx.x;
    const int b  = blockIdx.z;
    const int x0 = blockIdx.x * TW;
    const int y0 = blockIdx.y * TH;

    // ================= Phase A: stage weights + inputs into smem =================
    // mw1 rows: [0,10)=W_self, [10,20)=W_neigh, [20,23)=W_con, [23,55)=W_fn
    for (int i = tid; i < 640; i += NTHREADS) {
        const int row = i >> 6, pos = i & 63;
        const int jj = (pos >> 1) + ((pos & 1) << 5);
        sm[OFF_WSELF  + i] = mw1[row * 64 + jj];
        sm[OFF_WNEIGH + i] = mw1[640 + row * 64 + jj];
        sm[OFF_MW2T + i] = mw2[jj * 10 + row];
        sm[OFF_UW2T + i] = uw2[jj * 10 + row];
    }
    for (int i = tid; i < 192; i += NTHREADS) {
        const int row = i >> 6, pos = i & 63;
        const int jj = (pos >> 1) + ((pos & 1) << 5);
        sm[OFF_WC + i] = mw1[1280 + row * 64 + jj];
    }
    for (int i = tid; i < 1280; i += NTHREADS) {
        const int row = i >> 6, pos = i & 63;
        const int jj = (pos >> 1) + ((pos & 1) << 5);
        sm[OFF_UW1 + i] = uw1[row * 64 + jj];
    }
    if (tid < 64) {
        const int pos = 2 * (tid & 31) + (tid >> 5);   // pos(j=tid)
        sm[OFF_UB1 + pos] = ub1[tid];
        float s = mb1[tid];
        const float* f = fnembed + b * FD_;
        #pragma unroll
        for (int k = 0; k < FD_; ++k)
            s = fmaf(f[k], mw1[(23 + k) * HID_ + tid], s);
        sm[OFF_BASE + pos] = s;
    }
    if (tid >= 64 && tid < 74) {
        int k = tid - 64;
        sm[OFF_MB2   + k] = mb2[k];
        sm[OFF_UB2   + k] = ub2[k];
        sm[OFF_GAMMA + k] = gamma_[k];
        sm[OFF_BETA  + k] = beta_[k];
    }

    // beliefs halo (replicate-pad), rows stride 10
    for (int idx = tid; idx < NHALO * C_; idx += NTHREADS) {
        int p = idx / C_, i = idx - p * C_;
        int hr = p / HW, hc = p - hr * HW;
        int gy = min(max(y0 - 1 + hr, 0), H_ - 1);
        int gx = min(max(x0 - 1 + hc, 0), W_ - 1);
        sm[OFF_SB + p * 10 + i] = beliefs[((size_t)(b * H_ + gy) * W_ + gx) * C_ + i];
    }
    // constraints tile: coalesced float4 gmem reads, DUPLICATED (v,v) smem writes
    for (int idx = tid; idx < NPIX * 6; idx += NTHREADS) {
        int r = idx / (TW * 6), o = idx - r * (TW * 6);
        const float4 v = ((const float4*)(constraints +
            ((size_t)(b * H_ + y0 + r) * W_ + x0) * 24))[o];
        int pr = o / 6, e0 = (o - pr * 6) * 4;
        float* d = &sm[OFF_SC + (r * TW + pr) * 48 + 2 * e0];
        float2 w;
        w.x = v.x; w.y = v.x; *(float2*)&d[0] = w;
        w.x = v.y; w.y = v.y; *(float2*)&d[2] = w;
        w.x = v.z; w.y = v.z; *(float2*)&d[4] = w;
        w.x = v.w; w.y = v.w; *(float2*)&d[6] = w;
    }
    __syncthreads();

    const int lane = tid & 31;
    const int wrp  = tid >> 5;   // 0..15
    const int pp   = 2 * lane;   // float2 offset for this thread's (j, j+32) pair

    // ================= Phase B: y = beliefs @ W_neigh over halo =================
    {
        float2 wn[C_];
        #pragma unroll
        for (int i = 0; i < C_; ++i) wn[i] = *(const float2*)&sm[OFF_WNEIGH + i * 64 + pp];
        #pragma unroll 1
        for (int hp = wrp; hp < NHALO; hp += NWARP) {
            float2 sv[5];
            #pragma unroll
            for (int q = 0; q < 5; ++q) sv[q] = *(const float2*)&sm[OFF_SB + hp * 10 + 2 * q];
            // 2 chains per half
            float yx0 = 0.f, yx1 = 0.f, yy0 = 0.f, yy1 = 0.f;
            yx0 = fmaf(sv[0].x, wn[0].x, yx0); yy0 = fmaf(sv[0].x, wn[0].y, yy0);
            yx1 = fmaf(sv[0].y, wn[1].x, yx1); yy1 = fmaf(sv[0].y, wn[1].y, yy1);
            yx0 = fmaf(sv[1].x, wn[2].x, yx0); yy0 = fmaf(sv[1].x, wn[2].y, yy0);
            yx1 = fmaf(sv[1].y, wn[3].x, yx1); yy1 = fmaf(sv[1].y, wn[3].y, yy1);
            yx0 = fmaf(sv[2].x, wn[4].x, yx0); yy0 = fmaf(sv[2].x, wn[4].y, yy0);
            yx1 = fmaf(sv[2].y, wn[5].x, yx1); yy1 = fmaf(sv[2].y, wn[5].y, yy1);
            yx0 = fmaf(sv[3].x, wn[6].x, yx0); yy0 = fmaf(sv[3].x, wn[6].y, yy0);
            yx1 = fmaf(sv[3].y, wn[7].x, yx1); yy1 = fmaf(sv[3].y, wn[7].y, yy1);
            yx0 = fmaf(sv[4].x, wn[8].x, yx0); yy0 = fmaf(sv[4].x, wn[8].y, yy0);
            yx1 = fmaf(sv[4].y, wn[9].x, yx1); yy1 = fmaf(sv[4].y, wn[9].y, yy1);
            float2 y; y.x = yx0 + yx1; y.y = yy0 + yy1;
            *(float2*)&sm[OFF_SY + hp * HID_ + pp] = y;
        }
    }
    __syncthreads();

    // ================= Phase C: hs = sum_d relu(a + y_nb + c@wc), packed f32x2 ====
    {
        float2 ws[C_];
        #pragma unroll
        for (int i = 0; i < C_; ++i) ws[i] = *(const float2*)&sm[OFF_WSELF + i * 64 + pp];
        const uint64_t wc0 = *(const uint64_t*)&sm[OFF_WC + pp];
        const uint64_t wc1 = *(const uint64_t*)&sm[OFF_WC + 64 + pp];
        const uint64_t wc2 = *(const uint64_t*)&sm[OFF_WC + 128 + pp];
        const float2 bs  = *(const float2*)&sm[OFF_BASE + pp];

        const int row = wrp >> 1;            // 0..7
        const int xh  = (wrp & 1) * 16;      // x-half: 0 or 16
        const int rt = row * HW, rm = (row + 1) * HW, rb = (row + 2) * HW;

        // sliding 3x3 y-window as packed pairs (center slot 4 carried, unused)
        uint64_t yw[9];
        yw[0] = *(const uint64_t*)&sm[OFF_SY + (rt + xh + 0) * HID_ + pp];
        yw[1] = *(const uint64_t*)&sm[OFF_SY + (rt + xh + 1) * HID_ + pp];
        yw[3] = *(const uint64_t*)&sm[OFF_SY + (rm + xh + 0) * HID_ + pp];
        yw[4] = *(const uint64_t*)&sm[OFF_SY + (rm + xh + 1) * HID_ + pp];
        yw[6] = *(const uint64_t*)&sm[OFF_SY + (rb + xh + 0) * HID_ + pp];
        yw[7] = *(const uint64_t*)&sm[OFF_SY + (rb + xh + 1) * HID_ + pp];

        #pragma unroll 1
        for (int xi = 0; xi < 16; ++xi) {
            const int x = xh + xi;
            yw[2] = *(const uint64_t*)&sm[OFF_SY + (rt + x + 2) * HID_ + pp];
            yw[5] = *(const uint64_t*)&sm[OFF_SY + (rm + x + 2) * HID_ + pp];
            yw[8] = *(const uint64_t*)&sm[OFF_SY + (rb + x + 2) * HID_ + pp];

            const int p   = row * TW + x;
            const int hpc = rm + x + 1;

            // a = base + self @ W_self : 2 chains per half
            float2 sv[5];
            #pragma unroll
            for (int q = 0; q < 5; ++q) sv[q] = *(const float2*)&sm[OFF_SB + hpc * 10 + 2 * q];
            float ax0 = bs.x, ax1 = 0.f, ay0 = bs.y, ay1 = 0.f;
            ax0 = fmaf(sv[0].x, ws[0].x, ax0); ay0 = fmaf(sv[0].x, ws[0].y, ay0);
            ax1 = fmaf(sv[0].y, ws[1].x, ax1); ay1 = fmaf(sv[0].y, ws[1].y, ay1);
            ax0 = fmaf(sv[1].x, ws[2].x, ax0); ay0 = fmaf(sv[1].x, ws[2].y, ay0);
            ax1 = fmaf(sv[1].y, ws[3].x, ax1); ay1 = fmaf(sv[1].y, ws[3].y, ay1);
            ax0 = fmaf(sv[2].x, ws[4].x, ax0); ay0 = fmaf(sv[2].x, ws[4].y, ay0);
            ax1 = fmaf(sv[2].y, ws[5].x, ax1); ay1 = fmaf(sv[2].y, ws[5].y, ay1);
            ax0 = fmaf(sv[3].x, ws[6].x, ax0); ay0 = fmaf(sv[3].x, ws[6].y, ay0);
            ax1 = fmaf(sv[3].y, ws[7].x, ax1); ay1 = fmaf(sv[3].y, ws[7].y, ay1);
            ax0 = fmaf(sv[4].x, ws[8].x, ax0); ay0 = fmaf(sv[4].x, ws[8].y, ay0);
            ax1 = fmaf(sv[4].y, ws[9].x, ax1); ay1 = fmaf(sv[4].y, ws[9].y, ay1);
            const uint64_t a_pk = f2_pack(ax0 + ax1, ay0 + ay1);

            // d-loop: 4 direction-pairs, packed math, duplicated cc broadcasts
            const int DI[8] = {0,1,2,3,5,6,7,8};
            float mx[8], my[8];
            const float* cbase = &sm[OFF_SC + p * 48];
            #pragma unroll
            for (int dd = 0; dd < 4; ++dd) {
                const ulonglong2 q0 = *(const ulonglong2*)&cbase[dd * 12];
                const ulonglong2 q1 = *(const ulonglong2*)&cbase[dd * 12 + 4];
                const ulonglong2 q2 = *(const ulonglong2*)&cbase[dd * 12 + 8];
                uint64_t t0 = f2_add(a_pk, yw[DI[2*dd]]);
                t0 = f2_fma(q0.x, wc0, t0);
                t0 = f2_fma(q0.y, wc1, t0);
                t0 = f2_fma(q1.x, wc2, t0);
                uint64_t t1 = f2_add(a_pk, yw[DI[2*dd+1]]);
                t1 = f2_fma(q1.y, wc0, t1);
                t1 = f2_fma(q2.x, wc1, t1);
                t1 = f2_fma(q2.y, wc2, t1);
                float t0x, t0y, t1x, t1y;
                f2_unpack(t0, t0x, t0y);
                f2_unpack(t1, t1x, t1y);
                mx[2*dd]   = fmaxf(t0x, 0.f); my[2*dd]   = fmaxf(t0y, 0.f);
                mx[2*dd+1] = fmaxf(t1x, 0.f); my[2*dd+1] = fmaxf(t1y, 0.f);
            }
            // pairwise tree reduction (depth 3)
            float2 hs;
            hs.x = ((mx[0] + mx[1]) + (mx[2] + mx[3])) + ((mx[4] + mx[5]) + (mx[6] + mx[7]));
            hs.y = ((my[0] + my[1]) + (my[2] + my[3])) + ((my[4] + my[5]) + (my[6] + my[7]));
            *(float2*)&sm[OFF_SHS + p * HID_ + pp] = hs;

            yw[0]=yw[1]; yw[1]=yw[2];
            yw[3]=yw[4]; yw[4]=yw[5];
            yw[6]=yw[7]; yw[7]=yw[8];
        }
    }
    __syncthreads();

    // 8-lane-group mapping for phases D and F (pos-order)
    const int g    = lane >> 3;
    const int li   = lane & 7;
    const int j0   = li << 3;

    // ================= Phase D: agg = (mean_d relu)@mw2 + mb2 =================
    {
        float w2[10][8];   // register-resident across all passes
        #pragma unroll
        for (int k = 0; k < 10; ++k) {
            *(float4*)&w2[k][0] = *(const float4*)&sm[OFF_MW2T + k * 64 + j0];
            *(float4*)&w2[k][4] = *(const float4*)&sm[OFF_MW2T + k * 64 + j0 + 4];
        }
        float mb2r[10];
        #pragma unroll
        for (int k = 0; k < 10; ++k) mb2r[k] = sm[OFF_MB2 + k];

        #pragma unroll 1
        for (int pass = 0; pass < 4; ++pass) {
            const int p = pass * 64 + wrp * 4 + g;
            float hs[8];
            *(float4*)&hs[0] = *(const float4*)&sm[OFF_SHS + p * 64 + j0];
            *(float4*)&hs[4] = *(const float4*)&sm[OFF_SHS + p * 64 + j0 + 4];
            float agg[10];
            #pragma unroll
            for (int k = 0; k < 10; ++k) {
                float s0 = 0.f, s1 = 0.f;
                #pragma unroll
                for (int jj = 0; jj < 4; ++jj) {
                    s0 = fmaf(hs[jj],     w2[k][jj],     s0);
                    s1 = fmaf(hs[jj + 4], w2[k][jj + 4], s1);
                }
                agg[k] = s0 + s1;
            }
            #pragma unroll
            for (int o = 1; o < 8; o <<= 1) {
                #pragma unroll
                for (int k = 0; k < 10; ++k)
                    agg[k] += __shfl_xor_sync(0xffffffffu, agg[k], o);
            }
            if (li == 0) {
                #pragma unroll
                for (int k = 0; k < 10; k += 2) {
                    float2 v; v.x = fmaf(agg[k],   0.125f, mb2r[k]);
                              v.y = fmaf(agg[k+1], 0.125f, mb2r[k+1]);
                    *(float2*)&sm[OFF_SAGG + p * 12 + k] = v;
                }
            }
        }
    }
    __syncthreads();

    // ================= Phase E: u = relu([self,agg] @ uw1 + ub1) =================
    {
        float2 w1[20];     // uw1[:, pair] register-resident (40 regs)
        #pragma unroll
        for (int i = 0; i < 20; ++i) w1[i] = *(const float2*)&sm[OFF_UW1 + i * 64 + pp];
        const float2 b1 = *(const float2*)&sm[OFF_UB1 + pp];

        #pragma unroll 1
        for (int p = wrp; p < NPIX; p += NWARP) {
            const int hpc = ((p >> 5) + 1) * HW + (p & 31) + 1;
            float2 sv[5];
            #pragma unroll
            for (int q = 0; q < 5; ++q) sv[q] = *(const float2*)&sm[OFF_SB + hpc * 10 + 2 * q];
            const float4 a0 = *(const float4*)&sm[OFF_SAGG + p * 12];
            const float4 a1 = *(const float4*)&sm[OFF_SAGG + p * 12 + 4];
            const float2 a2 = *(const float2*)&sm[OFF_SAGG + p * 12 + 8];
            // 2 chains per half
            float ux0 = b1.x, ux1 = 0.f, uy0 = b1.y, uy1 = 0.f;
            ux0 = fmaf(sv[0].x, w1[0].x,  ux0); uy0 = fmaf(sv[0].x, w1[0].y,  uy0);
            ux1 = fmaf(sv[0].y, w1[1].x,  ux1); uy1 = fmaf(sv[0].y, w1[1].y,  uy1);
            ux0 = fmaf(sv[1].x, w1[2].x,  ux0); uy0 = fmaf(sv[1].x, w1[2].y,  uy0);
            ux1 = fmaf(sv[1].y, w1[3].x,  ux1); uy1 = fmaf(sv[1].y, w1[3].y,  uy1);
            ux0 = fmaf(sv[2].x, w1[4].x,  ux0); uy0 = fmaf(sv[2].x, w1[4].y,  uy0);
            ux1 = fmaf(sv[2].y, w1[5].x,  ux1); uy1 = fmaf(sv[2].y, w1[5].y,  uy1);
            ux0 = fmaf(sv[3].x, w1[6].x,  ux0); uy0 = fmaf(sv[3].x, w1[6].y,  uy0);
            ux1 = fmaf(sv[3].y, w1[7].x,  ux1); uy1 = fmaf(sv[3].y, w1[7].y,  uy1);
            ux0 = fmaf(sv[4].x, w1[8].x,  ux0); uy0 = fmaf(sv[4].x, w1[8].y,  uy0);
            ux1 = fmaf(sv[4].y, w1[9].x,  ux1); uy1 = fmaf(sv[4].y, w1[9].y,  uy1);
            ux0 = fmaf(a0.x, w1[10].x, ux0); uy0 = fmaf(a0.x, w1[10].y, uy0);
            ux1 = fmaf(a0.y, w1[11].x, ux1); uy1 = fmaf(a0.y, w1[11].y, uy1);
            ux0 = fmaf(a0.z, w1[12].x, ux0); uy0 = fmaf(a0.z, w1[12].y, uy0);
            ux1 = fmaf(a0.w, w1[13].x, ux1); uy1 = fmaf(a0.w, w1[13].y, uy1);
            ux0 = fmaf(a1.x, w1[14].x, ux0); uy0 = fmaf(a1.x, w1[14].y, uy0);
            ux1 = fmaf(a1.y, w1[15].x, ux1); uy1 = fmaf(a1.y, w1[15].y, uy1);
            ux0 = fmaf(a1.z, w1[16].x, ux0); uy0 = fmaf(a1.z, w1[16].y, uy0);
            ux1 = fmaf(a1.w, w1[17].x, ux1); uy1 = fmaf(a1.w, w1[17].y, uy1);
            ux0 = fmaf(a2.x, w1[18].x, ux0); uy0 = fmaf(a2.x, w1[18].y, uy0);
            ux1 = fmaf(a2.y, w1[19].x, ux1); uy1 = fmaf(a2.y, w1[19].y, uy1);
            float2 u; u.x = fmaxf(ux0 + ux1, 0.f); u.y = fmaxf(uy0 + uy1, 0.f);
            *(float2*)&sm[OFF_SU + p * 64 + pp] = u;
        }
    }
    __syncthreads();

    // ================= Phase F: upd = u @ uw2 + ub2 ; residual + LN =================
    {
        float w2[10][8];   // uw2t register-resident
        #pragma unroll
        for (int k = 0; k < 10; ++k) {
            *(float4*)&w2[k][0] = *(const float4*)&sm[OFF_UW2T + k * 64 + j0];
            *(float4*)&w2[k][4] = *(const float4*)&sm[OFF_UW2T + k * 64 + j0 + 4];
        }

        #pragma unroll 1
        for (int pass = 0; pass < 4; ++pass) {
            const int p = pass * 64 + wrp * 4 + g;
            float u[8];
            *(float4*)&u[0] = *(const float4*)&sm[OFF_SU + p * 64 + j0];
            *(float4*)&u[4] = *(const float4*)&sm[OFF_SU + p * 64 + j0 + 4];
            float upd[10];
            #pragma unroll
            for (int k = 0; k < 10; ++k) {
                float s0 = 0.f, s1 = 0.f;
                #pragma unroll
                for (int jj = 0; jj < 4; ++jj) {
                    s0 = fmaf(u[jj],     w2[k][jj],     s0);
                    s1 = fmaf(u[jj + 4], w2[k][jj + 4], s1);
                }
                upd[k] = s0 + s1;
            }
            #pragma unroll
            for (int o = 1; o < 8; o <<= 1) {
                #pragma unroll
                for (int k = 0; k < 10; ++k)
                    upd[k] += __shfl_xor_sync(0xffffffffu, upd[k], o);
            }
            if (li == 0) {
                const int hpc = ((p >> 5) + 1) * HW + (p & 31) + 1;
                float sf[10];
                #pragma unroll
                for (int q = 0; q < 5; ++q) {
                    const float2 v = *(const float2*)&sm[OFF_SB + hpc * 10 + 2 * q];
                    sf[2*q] = v.x; sf[2*q+1] = v.y;
                }
                float x[10]; float mu = 0.f;
                #pragma unroll
                for (int k = 0; k < 10; ++k) {
                    float xv = fmaf(0.5f, upd[k] + sm[OFF_UB2 + k], sf[k]);
                    x[k] = xv; mu += xv;
                }
                mu *= 0.1f;
                float var = 0.f;
                #pragma unroll
                for (int k = 0; k < 10; ++k) { float dk = x[k] - mu; var = fmaf(dk, dk, var); }
                const float inv = rsqrtf(var * 0.1f + 1e-5f);
                #pragma unroll
                for (int k = 0; k < 10; k += 2) {
                    float2 v;
                    v.x = fmaf((x[k]   - mu) * inv, sm[OFF_GAMMA + k],   sm[OFF_BETA + k]);
                    v.y = fmaf((x[k+1] - mu) * inv, sm[OFF_GAMMA + k+1], sm[OFF_BETA + k+1]);
                    *(float2*)&sm[OFF_SOUT + p * C_ + k] = v;
                }
            }
        }
    }
    __syncthreads();

    // ================= Phase G: coalesced float4 store =================
    {
        const float4* src = (const float4*)&sm[OFF_SOUT];
        for (int idx = tid; idx < NPIX * C_ / 4; idx += NTHREADS) {
            int r = idx / 80, o = idx - r * 80;
            float4* dst = (float4*)(out + ((size_t)(b * H_ + y0 + r) * W_ + x0) * C_);
            dst[o] = src[idx];
        }
    }
}

extern "C" void kernel_launch(void* const* d_in, const int* in_sizes, int n_in,
                              void* d_out, int out_size)
{
    const float* beliefs     = (const float*)d_in[0];
    const float* constraints = (const float*)d_in[1];
    const float* fnembed     = (const float*)d_in[2];
    const float* mw1         = (const float*)d_in[3];
    const float* mb1         = (const float*)d_in[4];
    const float* mw2         = (const float*)d_in[5];
    const float* mb2         = (const float*)d_in[6];
    const float* uw1         = (const float*)d_in[7];
    const float* ub1         = (const float*)d_in[8];
    const float* uw2         = (const float*)d_in[9];
    const float* ub2         = (const float*)d_in[10];
    const float* gamma_      = (const float*)d_in[11];
    const float* beta_       = (const float*)d_in[12];
    float* out = (float*)d_out;

    cudaFuncSetAttribute(cmp_kernel, cudaFuncAttributeMaxDynamicSharedMemorySize, SMEM_BYTES);

    dim3 grid(W_ / TW, H_ / TH, B_);
    cmp_kernel<<<grid, NTHREADS, SMEM_BYTES>>>(
        beliefs, constraints, fnembed, mw1, mb1, mw2, mb2,
        uw1, ub1, uw2, ub2, gamma_, beta_, out);
}

// round 10
// speedup vs baseline: 1.0294x; 1.0294x over previous
#include <cuda_runtime.h>
#include <cstdint>

// Problem constants
#define B_  64
#define H_  128
#define W_  128
#define C_  10
#define FD_ 32
#define HID_ 64

// Tile config
#define TW 32
#define TH 8
#define HW 34   // halo width  (TW+2)
#define HH 10   // halo height (TH+2)
#define NPIX  (TW*TH)   // 256
#define NHALO (HW*HH)   // 340
#define NTHREADS 512
#define NWARP 16

// Hidden-dim "pos" layout: pos(j) = 2*(j&31) + (j>>5); j(pos) = (pos>>1) + (pos&1)*32
// y / hs / u arrays and per-j weights are stored in pos order: a warp lane owns
// the pair (j=lane, j=lane+32) as one float2 at float-offset 2*lane.

// Shared memory layout (float offsets). Regions reused across phases:
//   SOUT aliases SY  (SY dead after phase C)
//   SAGG aliases SC  (SC dead after phase C)
//   SU   aliases SHS (SHS dead after phase D)
#define OFF_SY     0                          // NHALO*64 = 21760
#define OFF_SOUT   OFF_SY
#define OFF_SB     (OFF_SY + NHALO*HID_)      // rows padded to 12
#define OFF_SC     (OFF_SB + NHALO*12)        // NPIX*24
#define OFF_SAGG   OFF_SC                     // NPIX*12
#define OFF_SHS    (OFF_SC + NPIX*24)         // NPIX*64
#define OFF_SU     OFF_SHS
#define OFF_WSELF  (OFF_SHS + NPIX*HID_)      // pos-interleaved
#define OFF_WNEIGH (OFF_WSELF + 640)          // pos-interleaved
#define OFF_WC     (OFF_WNEIGH + 640)         // pos-interleaved
#define OFF_MW2T   (OFF_WC + 192)             // [k][pos]
#define OFF_UW2T   (OFF_MW2T + 640)           // [k][pos]
#define OFF_UW1    (OFF_UW2T + 640)           // pos-interleaved
#define OFF_UB1    (OFF_UW1 + 1280)           // pos-interleaved
#define OFF_BASE   (OFF_UB1 + 64)             // pos-interleaved
#define OFF_MB2    (OFF_BASE + 64)
#define OFF_UB2    (OFF_MB2 + 12)
#define OFF_GAMMA  (OFF_UB2 + 12)
#define OFF_BETA   (OFF_GAMMA + 12)
#define SMEM_FLOATS (OFF_BETA + 12)
#define SMEM_BYTES  (SMEM_FLOATS * 4)         // 210496

__global__ void __launch_bounds__(NTHREADS, 1)
cmp_kernel(const float* __restrict__ beliefs,
           const float* __restrict__ constraints,
           const float* __restrict__ fnembed,
           const float* __restrict__ mw1, const float* __restrict__ mb1,
           const float* __restrict__ mw2, const float* __restrict__ mb2,
           const float* __restrict__ uw1, const float* __restrict__ ub1,
           const float* __restrict__ uw2, const float* __restrict__ ub2,
           const float* __restrict__ gamma_, const float* __restrict__ beta_,
           float* __restrict__ out)
{
    extern __shared__ __align__(16) float sm[];
    const int tid = threadIdx.x;
    const int b  = blockIdx.z;
    const int x0 = blockIdx.x * TW;
    const int y0 = blockIdx.y * TH;

    // ================= Phase A: stage weights + inputs into smem =================
    // mw1 rows: [0,10)=W_self, [10,20)=W_neigh, [20,23)=W_con, [23,55)=W_fn
    for (int i = tid; i < 640; i += NTHREADS) {
        const int row = i >> 6, pos = i & 63;
        const int jj = (pos >> 1) + ((pos & 1) << 5);
        sm[OFF_WSELF  + i] = mw1[row * 64 + jj];
        sm[OFF_WNEIGH + i] = mw1[640 + row * 64 + jj];
        sm[OFF_MW2T + i] = mw2[jj * 10 + row];
        sm[OFF_UW2T + i] = uw2[jj * 10 + row];
    }
    for (int i = tid; i < 192; i += NTHREADS) {
        const int row = i >> 6, pos = i & 63;
        const int jj = (pos >> 1) + ((pos & 1) << 5);
        sm[OFF_WC + i] = mw1[1280 + row * 64 + jj];
    }
    for (int i = tid; i < 1280; i += NTHREADS) {
        const int row = i >> 6, pos = i & 63;
        const int jj = (pos >> 1) + ((pos & 1) << 5);
        sm[OFF_UW1 + i] = uw1[row * 64 + jj];
    }
    if (tid < 64) {
        const int pos = 2 * (tid & 31) + (tid >> 5);   // pos(j=tid)
        sm[OFF_UB1 + pos] = ub1[tid];
        float s = mb1[tid];
        const float* f = fnembed + b * FD_;
        #pragma unroll
        for (int k = 0; k < FD_; ++k)
            s = fmaf(f[k], mw1[(23 + k) * HID_ + tid], s);
        sm[OFF_BASE + pos] = s;
    }
    if (tid >= 64 && tid < 74) {
        int k = tid - 64;
        sm[OFF_MB2   + k] = mb2[k];
        sm[OFF_UB2   + k] = ub2[k];
        sm[OFF_GAMMA + k] = gamma_[k];
        sm[OFF_BETA  + k] = beta_[k];
    }

    // beliefs halo (replicate-pad), rows padded to 12 floats
    for (int idx = tid; idx < NHALO * C_; idx += NTHREADS) {
        int p = idx / C_, i = idx - p * C_;
        int hr = p / HW, hc = p - hr * HW;
        int gy = min(max(y0 - 1 + hr, 0), H_ - 1);
        int gx = min(max(x0 - 1 + hc, 0), W_ - 1);
        sm[OFF_SB + p * 12 + i] = beliefs[((size_t)(b * H_ + gy) * W_ + gx) * C_ + i];
    }
    // constraints tile (float4, coalesced)
    {
        float4* dst = (float4*)&sm[OFF_SC];
        for (int idx = tid; idx < NPIX * 6; idx += NTHREADS) {
            int r = idx / (TW * 6), o = idx - r * (TW * 6);
            const float4* src = (const float4*)(constraints +
                ((size_t)(b * H_ + y0 + r) * W_ + x0) * 24);
            dst[idx] = src[o];
        }
    }
    __syncthreads();

    const int lane = tid & 31;
    const int wrp  = tid >> 5;   // 0..15
    const int pp   = 2 * lane;   // float2 offset for this thread's (j, j+32) pair

    // ================= Phase B: y = beliefs @ W_neigh over halo =================
    {
        float2 wn[C_];
        #pragma unroll
        for (int i = 0; i < C_; ++i) wn[i] = *(const float2*)&sm[OFF_WNEIGH + i * 64 + pp];
        #pragma unroll 2
        for (int hp = wrp; hp < NHALO; hp += NWARP) {
            const float4 s0 = *(const float4*)&sm[OFF_SB + hp * 12];
            const float4 s1 = *(const float4*)&sm[OFF_SB + hp * 12 + 4];
            const float2 s2 = *(const float2*)&sm[OFF_SB + hp * 12 + 8];
            float yx0 = 0.f, yx1 = 0.f, yy0 = 0.f, yy1 = 0.f;
            yx0 = fmaf(s0.x, wn[0].x, yx0); yy0 = fmaf(s0.x, wn[0].y, yy0);
            yx1 = fmaf(s0.y, wn[1].x, yx1); yy1 = fmaf(s0.y, wn[1].y, yy1);
            yx0 = fmaf(s0.z, wn[2].x, yx0); yy0 = fmaf(s0.z, wn[2].y, yy0);
            yx1 = fmaf(s0.w, wn[3].x, yx1); yy1 = fmaf(s0.w, wn[3].y, yy1);
            yx0 = fmaf(s1.x, wn[4].x, yx0); yy0 = fmaf(s1.x, wn[4].y, yy0);
            yx1 = fmaf(s1.y, wn[5].x, yx1); yy1 = fmaf(s1.y, wn[5].y, yy1);
            yx0 = fmaf(s1.z, wn[6].x, yx0); yy0 = fmaf(s1.z, wn[6].y, yy0);
            yx1 = fmaf(s1.w, wn[7].x, yx1); yy1 = fmaf(s1.w, wn[7].y, yy1);
            yx0 = fmaf(s2.x, wn[8].x, yx0); yy0 = fmaf(s2.x, wn[8].y, yy0);
            yx1 = fmaf(s2.y, wn[9].x, yx1); yy1 = fmaf(s2.y, wn[9].y, yy1);
            float2 y; y.x = yx0 + yx1; y.y = yy0 + yy1;
            *(float2*)&sm[OFF_SY + hp * HID_ + pp] = y;
        }
    }
    __syncthreads();

    // ================= Phase C: hs = sum_d relu(a + y_nb + c@wc), 2 px / iter ====
    {
        float2 ws[C_];
        #pragma unroll
        for (int i = 0; i < C_; ++i) ws[i] = *(const float2*)&sm[OFF_WSELF + i * 64 + pp];
        const float2 wc0 = *(const float2*)&sm[OFF_WC + pp];
        const float2 wc1 = *(const float2*)&sm[OFF_WC + 64 + pp];
        const float2 wc2 = *(const float2*)&sm[OFF_WC + 128 + pp];
        const float2 bs  = *(const float2*)&sm[OFF_BASE + pp];

        const int row = wrp >> 1;            // 0..7
        const int xh  = (wrp & 1) * 16;      // x-half: 0 or 16
        const int rt = row * HW, rm = (row + 1) * HW, rb = (row + 2) * HW;

        // sliding 3x4 y-window: yw[r*4+c], col c = halo col x+c (r: 0=t,1=m,2=b)
        float2 yw[12];
        yw[0] = *(const float2*)&sm[OFF_SY + (rt + xh + 0) * HID_ + pp];
        yw[1] = *(const float2*)&sm[OFF_SY + (rt + xh + 1) * HID_ + pp];
        yw[4] = *(const float2*)&sm[OFF_SY + (rm + xh + 0) * HID_ + pp];
        yw[5] = *(const float2*)&sm[OFF_SY + (rm + xh + 1) * HID_ + pp];
        yw[8] = *(const float2*)&sm[OFF_SY + (rb + xh + 0) * HID_ + pp];
        yw[9] = *(const float2*)&sm[OFF_SY + (rb + xh + 1) * HID_ + pp];

        #pragma unroll 1
        for (int xi = 0; xi < 16; xi += 2) {
            const int x = xh + xi;
            yw[2]  = *(const float2*)&sm[OFF_SY + (rt + x + 2) * HID_ + pp];
            yw[3]  = *(const float2*)&sm[OFF_SY + (rt + x + 3) * HID_ + pp];
            yw[6]  = *(const float2*)&sm[OFF_SY + (rm + x + 2) * HID_ + pp];
            yw[7]  = *(const float2*)&sm[OFF_SY + (rm + x + 3) * HID_ + pp];
            yw[10] = *(const float2*)&sm[OFF_SY + (rb + x + 2) * HID_ + pp];
            yw[11] = *(const float2*)&sm[OFF_SY + (rb + x + 3) * HID_ + pp];

            const int p   = row * TW + x;
            const int hpc = rm + x + 1;

            // a for px0 and px1 (two independent 2-chain GEMVs)
            float2 a0, a1;
            {
                const float4 s0 = *(const float4*)&sm[OFF_SB + hpc * 12];
                const float4 s1 = *(const float4*)&sm[OFF_SB + hpc * 12 + 4];
                const float2 s2 = *(const float2*)&sm[OFF_SB + hpc * 12 + 8];
                float ax0 = bs.x, ax1 = 0.f, ay0 = bs.y, ay1 = 0.f;
                ax0 = fmaf(s0.x, ws[0].x, ax0); ay0 = fmaf(s0.x, ws[0].y, ay0);
                ax1 = fmaf(s0.y, ws[1].x, ax1); ay1 = fmaf(s0.y, ws[1].y, ay1);
                ax0 = fmaf(s0.z, ws[2].x, ax0); ay0 = fmaf(s0.z, ws[2].y, ay0);
                ax1 = fmaf(s0.w, ws[3].x, ax1); ay1 = fmaf(s0.w, ws[3].y, ay1);
                ax0 = fmaf(s1.x, ws[4].x, ax0); ay0 = fmaf(s1.x, ws[4].y, ay0);
                ax1 = fmaf(s1.y, ws[5].x, ax1); ay1 = fmaf(s1.y, ws[5].y, ay1);
                ax0 = fmaf(s1.z, ws[6].x, ax0); ay0 = fmaf(s1.z, ws[6].y, ay0);
                ax1 = fmaf(s1.w, ws[7].x, ax1); ay1 = fmaf(s1.w, ws[7].y, ay1);
                ax0 = fmaf(s2.x, ws[8].x, ax0); ay0 = fmaf(s2.x, ws[8].y, ay0);
                ax1 = fmaf(s2.y, ws[9].x, ax1); ay1 = fmaf(s2.y, ws[9].y, ay1);
                a0.x = ax0 + ax1; a0.y = ay0 + ay1;
            }
            {
                const float4 s0 = *(const float4*)&sm[OFF_SB + (hpc + 1) * 12];
                const float4 s1 = *(const float4*)&sm[OFF_SB + (hpc + 1) * 12 + 4];
                const float2 s2 = *(const float2*)&sm[OFF_SB + (hpc + 1) * 12 + 8];
                float ax0 = bs.x, ax1 = 0.f, ay0 = bs.y, ay1 = 0.f;
                ax0 = fmaf(s0.x, ws[0].x, ax0); ay0 = fmaf(s0.x, ws[0].y, ay0);
                ax1 = fmaf(s0.y, ws[1].x, ax1); ay1 = fmaf(s0.y, ws[1].y, ay1);
                ax0 = fmaf(s0.z, ws[2].x, ax0); ay0 = fmaf(s0.z, ws[2].y, ay0);
                ax1 = fmaf(s0.w, ws[3].x, ax1); ay1 = fmaf(s0.w, ws[3].y, ay1);
                ax0 = fmaf(s1.x, ws[4].x, ax0); ay0 = fmaf(s1.x, ws[4].y, ay0);
                ax1 = fmaf(s1.y, ws[5].x, ax1); ay1 = fmaf(s1.y, ws[5].y, ay1);
                ax0 = fmaf(s1.z, ws[6].x, ax0); ay0 = fmaf(s1.z, ws[6].y, ay0);
                ax1 = fmaf(s1.w, ws[7].x, ax1); ay1 = fmaf(s1.w, ws[7].y, ay1);
                ax0 = fmaf(s2.x, ws[8].x, ax0); ay0 = fmaf(s2.x, ws[8].y, ay0);
                ax1 = fmaf(s2.y, ws[9].x, ax1); ay1 = fmaf(s2.y, ws[9].y, ay1);
                a1.x = ax0 + ax1; a1.y = ay0 + ay1;
            }

            // window indices for the 8 directions of each pixel
            const int W0[8] = {0,1,2, 4,6, 8,9,10};    // px0 (cols 0..2)
            const int W1[8] = {1,2,3, 5,7, 9,10,11};   // px1 (cols 1..3)

            float hxA0 = 0.f, hxB0 = 0.f, hyA0 = 0.f, hyB0 = 0.f;
            float hxA1 = 0.f, hxB1 = 0.f, hyA1 = 0.f, hyB1 = 0.f;
            const float* cp0 = &sm[OFF_SC + p * 24];
            const float* cp1 = cp0 + 24;

            #pragma unroll
            for (int dd = 0; dd < 4; ++dd) {
                // px0, direction pair (2dd, 2dd+1)
                {
                    const float4 v0 = *(const float4*)&cp0[6 * dd];
                    const float2 v1 = *(const float2*)&cp0[6 * dd + 4];
                    const float2 yn0 = yw[W0[2*dd]];
                    const float2 yn1 = yw[W0[2*dd+1]];
                    float t0x = a0.x + yn0.x, t0y = a0.y + yn0.y;
                    t0x = fmaf(v0.x, wc0.x, t0x); t0y = fmaf(v0.x, wc0.y, t0y);
                    t0x = fmaf(v0.y, wc1.x, t0x); t0y = fmaf(v0.y, wc1.y, t0y);
                    t0x = fmaf(v0.z, wc2.x, t0x); t0y = fmaf(v0.z, wc2.y, t0y);
                    float t1x = a0.x + yn1.x, t1y = a0.y + yn1.y;
                    t1x = fmaf(v0.w, wc0.x, t1x); t1y = fmaf(v0.w, wc0.y, t1y);
                    t1x = fmaf(v1.x, wc1.x, t1x); t1y = fmaf(v1.x, wc1.y, t1y);
                    t1x = fmaf(v1.y, wc2.x, t1x); t1y = fmaf(v1.y, wc2.y, t1y);
                    if (dd & 1) { hxB0 += fmaxf(t0x,0.f) + fmaxf(t1x,0.f);
                                  hyB0 += fmaxf(t0y,0.f) + fmaxf(t1y,0.f); }
                    else        { hxA0 += fmaxf(t0x,0.f) + fmaxf(t1x,0.f);
                                  hyA0 += fmaxf(t0y,0.f) + fmaxf(t1y,0.f); }
                }
                // px1, direction pair (2dd, 2dd+1)
                {
                    const float4 v0 = *(const float4*)&cp1[6 * dd];
                    const float2 v1 = *(const float2*)&cp1[6 * dd + 4];
                    const float2 yn0 = yw[W1[2*dd]];
                    const float2 yn1 = yw[W1[2*dd+1]];
                    float t0x = a1.x + yn0.x, t0y = a1.y + yn0.y;
                    t0x = fmaf(v0.x, wc0.x, t0x); t0y = fmaf(v0.x, wc0.y, t0y);
                    t0x = fmaf(v0.y, wc1.x, t0x); t0y = fmaf(v0.y, wc1.y, t0y);
                    t0x = fmaf(v0.z, wc2.x, t0x); t0y = fmaf(v0.z, wc2.y, t0y);
                    float t1x = a1.x + yn1.x, t1y = a1.y + yn1.y;
                    t1x = fmaf(v0.w, wc0.x, t1x); t1y = fmaf(v0.w, wc0.y, t1y);
                    t1x = fmaf(v1.x, wc1.x, t1x); t1y = fmaf(v1.x, wc1.y, t1y);
                    t1x = fmaf(v1.y, wc2.x, t1x); t1y = fmaf(v1.y, wc2.y, t1y);
                    if (dd & 1) { hxB1 += fmaxf(t0x,0.f) + fmaxf(t1x,0.f);
                                  hyB1 += fmaxf(t0y,0.f) + fmaxf(t1y,0.f); }
                    else        { hxA1 += fmaxf(t0x,0.f) + fmaxf(t1x,0.f);
                                  hyA1 += fmaxf(t0y,0.f) + fmaxf(t1y,0.f); }
                }
            }
            float2 hs0; hs0.x = hxA0 + hxB0; hs0.y = hyA0 + hyB0;
            float2 hs1; hs1.x = hxA1 + hxB1; hs1.y = hyA1 + hyB1;
            *(float2*)&sm[OFF_SHS + p * HID_ + pp] = hs0;
            *(float2*)&sm[OFF_SHS + (p + 1) * HID_ + pp] = hs1;

            // shift window left by 2
            yw[0] = yw[2];  yw[1] = yw[3];
            yw[4] = yw[6];  yw[5] = yw[7];
            yw[8] = yw[10]; yw[9] = yw[11];
        }
    }
    __syncthreads();

    // 8-lane-group mapping for phases D and F (pos-order)
    const int g    = lane >> 3;
    const int li   = lane & 7;
    const int j0   = li << 3;

    // ================= Phase D: agg = (mean_d relu)@mw2 + mb2 =================
    {
        float w2[10][8];   // register-resident across all passes
        #pragma unroll
        for (int k = 0; k < 10; ++k) {
            *(float4*)&w2[k][0] = *(const float4*)&sm[OFF_MW2T + k * 64 + j0];
            *(float4*)&w2[k][4] = *(const float4*)&sm[OFF_MW2T + k * 64 + j0 + 4];
        }
        float mb2r[10];
        #pragma unroll
        for (int k = 0; k < 10; ++k) mb2r[k] = sm[OFF_MB2 + k];

        #pragma unroll 1
        for (int pass = 0; pass < 4; ++pass) {
            const int p = pass * 64 + wrp * 4 + g;
            float hs[8];
            *(float4*)&hs[0] = *(const float4*)&sm[OFF_SHS + p * 64 + j0];
            *(float4*)&hs[4] = *(const float4*)&sm[OFF_SHS + p * 64 + j0 + 4];
            float agg[10];
            #pragma unroll
            for (int k = 0; k < 10; ++k) {
                float s0 = 0.f, s1 = 0.f;
                #pragma unroll
                for (int jj = 0; jj < 4; ++jj) {
                    s0 = fmaf(hs[jj],     w2[k][jj],     s0);
                    s1 = fmaf(hs[jj + 4], w2[k][jj + 4], s1);
                }
                agg[k] = s0 + s1;
            }
            #pragma unroll
            for (int o = 1; o < 8; o <<= 1) {
                #pragma unroll
                for (int k = 0; k < 10; ++k)
                    agg[k] += __shfl_xor_sync(0xffffffffu, agg[k], o);
            }
            if (li == 0) {
                #pragma unroll
                for (int k = 0; k < 10; k += 2) {
                    float2 v; v.x = fmaf(agg[k],   0.125f, mb2r[k]);
                              v.y = fmaf(agg[k+1], 0.125f, mb2r[k+1]);
                    *(float2*)&sm[OFF_SAGG + p * 12 + k] = v;
                }
            }
        }
    }
    __syncthreads();

    // ================= Phase E: u = relu([self,agg] @ uw1 + ub1) =================
    {
        float2 w1[20];     // uw1[:, pair] register-resident (40 regs)
        #pragma unroll
        for (int i = 0; i < 20; ++i) w1[i] = *(const float2*)&sm[OFF_UW1 + i * 64 + pp];
        const float2 b1 = *(const float2*)&sm[OFF_UB1 + pp];

        #pragma unroll 2
        for (int p = wrp; p < NPIX; p += NWARP) {
            const int hpc = ((p >> 5) + 1) * HW + (p & 31) + 1;
            const float4 s0 = *(const float4*)&sm[OFF_SB + hpc * 12];
            const float4 s1 = *(const float4*)&sm[OFF_SB + hpc * 12 + 4];
            const float2 s2 = *(const float2*)&sm[OFF_SB + hpc * 12 + 8];
            const float4 a0 = *(const float4*)&sm[OFF_SAGG + p * 12];
            const float4 a1 = *(const float4*)&sm[OFF_SAGG + p * 12 + 4];
            const float2 a2 = *(const float2*)&sm[OFF_SAGG + p * 12 + 8];
            float ux0 = b1.x, ux1 = 0.f, uy0 = b1.y, uy1 = 0.f;
            ux0 = fmaf(s0.x, w1[0].x,  ux0); uy0 = fmaf(s0.x, w1[0].y,  uy0);
            ux1 = fmaf(s0.y, w1[1].x,  ux1); uy1 = fmaf(s0.y, w1[1].y,  uy1);
            ux0 = fmaf(s0.z, w1[2].x,  ux0); uy0 = fmaf(s0.z, w1[2].y,  uy0);
            ux1 = fmaf(s0.w, w1[3].x,  ux1); uy1 = fmaf(s0.w, w1[3].y,  uy1);
            ux0 = fmaf(s1.x, w1[4].x,  ux0); uy0 = fmaf(s1.x, w1[4].y,  uy0);
            ux1 = fmaf(s1.y, w1[5].x,  ux1); uy1 = fmaf(s1.y, w1[5].y,  uy1);
            ux0 = fmaf(s1.z, w1[6].x,  ux0); uy0 = fmaf(s1.z, w1[6].y,  uy0);
            ux1 = fmaf(s1.w, w1[7].x,  ux1); uy1 = fmaf(s1.w, w1[7].y,  uy1);
            ux0 = fmaf(s2.x, w1[8].x,  ux0); uy0 = fmaf(s2.x, w1[8].y,  uy0);
            ux1 = fmaf(s2.y, w1[9].x,  ux1); uy1 = fmaf(s2.y, w1[9].y,  uy1);
            ux0 = fmaf(a0.x, w1[10].x, ux0); uy0 = fmaf(a0.x, w1[10].y, uy0);
            ux1 = fmaf(a0.y, w1[11].x, ux1); uy1 = fmaf(a0.y, w1[11].y, uy1);
            ux0 = fmaf(a0.z, w1[12].x, ux0); uy0 = fmaf(a0.z, w1[12].y, uy0);
            ux1 = fmaf(a0.w, w1[13].x, ux1); uy1 = fmaf(a0.w, w1[13].y, uy1);
            ux0 = fmaf(a1.x, w1[14].x, ux0); uy0 = fmaf(a1.x, w1[14].y, uy0);
            ux1 = fmaf(a1.y, w1[15].x, ux1); uy1 = fmaf(a1.y, w1[15].y, uy1);
            ux0 = fmaf(a1.z, w1[16].x, ux0); uy0 = fmaf(a1.z, w1[16].y, uy0);
            ux1 = fmaf(a1.w, w1[17].x, ux1); uy1 = fmaf(a1.w, w1[17].y, uy1);
            ux0 = fmaf(a2.x, w1[18].x, ux0); uy0 = fmaf(a2.x, w1[18].y, uy0);
            ux1 = fmaf(a2.y, w1[19].x, ux1); uy1 = fmaf(a2.y, w1[19].y, uy1);
            float2 u; u.x = fmaxf(ux0 + ux1, 0.f); u.y = fmaxf(uy0 + uy1, 0.f);
            *(float2*)&sm[OFF_SU + p * 64 + pp] = u;
        }
    }
    __syncthreads();

    // ================= Phase F: upd = u @ uw2 + ub2 ; residual + LN =================
    {
        float w2[10][8];   // uw2t register-resident
        #pragma unroll
        for (int k = 0; k < 10; ++k) {
            *(float4*)&w2[k][0] = *(const float4*)&sm[OFF_UW2T + k * 64 + j0];
            *(float4*)&w2[k][4] = *(const float4*)&sm[OFF_UW2T + k * 64 + j0 + 4];
        }

        #pragma unroll 1
        for (int pass = 0; pass < 4; ++pass) {
            const int p = pass * 64 + wrp * 4 + g;
            float u[8];
            *(float4*)&u[0] = *(const float4*)&sm[OFF_SU + p * 64 + j0];
            *(float4*)&u[4] = *(const float4*)&sm[OFF_SU + p * 64 + j0 + 4];
            float upd[10];
            #pragma unroll
            for (int k = 0; k < 10; ++k) {
                float s0 = 0.f, s1 = 0.f;
                #pragma unroll
                for (int jj = 0; jj < 4; ++jj) {
                    s0 = fmaf(u[jj],     w2[k][jj],     s0);
                    s1 = fmaf(u[jj + 4], w2[k][jj + 4], s1);
                }
                upd[k] = s0 + s1;
            }
            #pragma unroll
            for (int o = 1; o < 8; o <<= 1) {
                #pragma unroll
                for (int k = 0; k < 10; ++k)
                    upd[k] += __shfl_xor_sync(0xffffffffu, upd[k], o);
            }
            if (li == 0) {
                const int hpc = ((p >> 5) + 1) * HW + (p & 31) + 1;
                const float4 s0 = *(const float4*)&sm[OFF_SB + hpc * 12];
                const float4 s1 = *(const float4*)&sm[OFF_SB + hpc * 12 + 4];
                const float2 s2 = *(const float2*)&sm[OFF_SB + hpc * 12 + 8];
                float sf[10] = {s0.x,s0.y,s0.z,s0.w,s1.x,s1.y,s1.z,s1.w,s2.x,s2.y};
                float x[10]; float mu = 0.f;
                #pragma unroll
                for (int k = 0; k < 10; ++k) {
                    float xv = fmaf(0.5f, upd[k] + sm[OFF_UB2 + k], sf[k]);
                    x[k] = xv; mu += xv;
                }
                mu *= 0.1f;
                float var = 0.f;
                #pragma unroll
                for (int k = 0; k < 10; ++k) { float dk = x[k] - mu; var = fmaf(dk, dk, var); }
                const float inv = rsqrtf(var * 0.1f + 1e-5f);
                #pragma unroll
                for (int k = 0; k < 10; k += 2) {
                    float2 v;
                    v.x = fmaf((x[k]   - mu) * inv, sm[OFF_GAMMA + k],   sm[OFF_BETA + k]);
                    v.y = fmaf((x[k+1] - mu) * inv, sm[OFF_GAMMA + k+1], sm[OFF_BETA + k+1]);
                    *(float2*)&sm[OFF_SOUT + p * C_ + k] = v;
                }
            }
        }
    }
    __syncthreads();

    // ================= Phase G: coalesced float4 store =================
    {
        const float4* src = (const float4*)&sm[OFF_SOUT];
        for (int idx = tid; idx < NPIX * C_ / 4; idx += NTHREADS) {
            int r = idx / 80, o = idx - r * 80;
            float4* dst = (float4*)(out + ((size_t)(b * H_ + y0 + r) * W_ + x0) * C_);
            dst[o] = src[idx];
        }
    }
}

extern "C" void kernel_launch(void* const* d_in, const int* in_sizes, int n_in,
                              void* d_out, int out_size)
{
    const float* beliefs     = (const float*)d_in[0];
    const float* constraints = (const float*)d_in[1];
    const float* fnembed     = (const float*)d_in[2];
    const float* mw1         = (const float*)d_in[3];
    const float* mb1         = (const float*)d_in[4];
    const float* mw2         = (const float*)d_in[5];
    const float* mb2         = (const float*)d_in[6];
    const float* uw1         = (const float*)d_in[7];
    const float* ub1         = (const float*)d_in[8];
    const float* uw2         = (const float*)d_in[9];
    const float* ub2         = (const float*)d_in[10];
    const float* gamma_      = (const float*)d_in[11];
    const float* beta_       = (const float*)d_in[12];
    float* out = (float*)d_out;

    cudaFuncSetAttribute(cmp_kernel, cudaFuncAttributeMaxDynamicSharedMemorySize, SMEM_BYTES);

    dim3 grid(W_ / TW, H_ / TH, B_);
    cmp_kernel<<<grid, NTHREADS, SMEM_BYTES>>>(
        beliefs, constraints, fnembed, mw1, mb1, mw2, mb2,
        uw1, ub1, uw2, ub2, gamma_, beta_, out);
}

// round 11
// speedup vs baseline: 1.1261x; 1.0940x over previous
#include <cuda_runtime.h>
#include <cstdint>

// Problem constants
#define B_  64
#define H_  128
#define W_  128
#define C_  10
#define FD_ 32
#define HID_ 64

// Tile config: 16x8 tile, 256 threads, 2 CTAs/SM
#define TW 16
#define TH 8
#define HW 18   // halo width  (TW+2)
#define HH 10   // halo height (TH+2)
#define NPIX  (TW*TH)   // 128
#define NHALO (HW*HH)   // 180
#define NTHREADS 256
#define NWARP 8

// Hidden-dim "pos" layout: pos(j) = 2*(j&31) + (j>>5); j(pos) = (pos>>1) + (pos&1)*32
// y / hs / u arrays and per-j weights are stored in pos order: a warp lane owns
// the pair (j=lane, j=lane+32) as one float2 at float-offset 2*lane.

// Shared memory layout (float offsets). Regions reused across phases:
//   SOUT aliases SY        (SY dead after phase C)
//   SAGG aliases SC[0:1536]   (SC dead after phase C)
//   UW1X aliases SC[1536:2816] (staged from gmem between C and E)
//   SU   aliases SHS       (SHS dead after phase D)
#define OFF_SY     0                          // NHALO*64 = 11520
#define OFF_SOUT   OFF_SY
#define OFF_SB     (OFF_SY + NHALO*HID_)      // 11520 ; rows padded to 12 (2160)
#define OFF_SC     (OFF_SB + NHALO*12)        // 13680 ; NPIX*24 = 3072
#define OFF_SAGG   OFF_SC                     // NPIX*12 = 1536
#define OFF_UW1X   (OFF_SC + 1536)            // 1280 (fits in SC upper half)
#define OFF_SHS    (OFF_SC + NPIX*24)         // 16752 ; NPIX*64 = 8192
#define OFF_SU     OFF_SHS
#define OFF_WSELF  (OFF_SHS + NPIX*HID_)      // 24944 ; pos-interleaved
#define OFF_WNEIGH (OFF_WSELF + 640)
#define OFF_WC     (OFF_WNEIGH + 640)
#define OFF_MW2T   (OFF_WC + 192)             // [k][pos]
#define OFF_UW2T   (OFF_MW2T + 640)           // [k][pos]
#define OFF_UB1    (OFF_UW2T + 640)           // pos-interleaved
#define OFF_BASE   (OFF_UB1 + 64)             // pos-interleaved
#define OFF_MB2    (OFF_BASE + 64)
#define OFF_UB2    (OFF_MB2 + 12)
#define OFF_GAMMA  (OFF_UB2 + 12)
#define OFF_BETA   (OFF_GAMMA + 12)
#define SMEM_FLOATS (OFF_BETA + 12)           // 27872
#define SMEM_BYTES  (SMEM_FLOATS * 4)         // 111488 -> 2 CTAs/SM

__global__ void __launch_bounds__(NTHREADS, 2)
cmp_kernel(const float* __restrict__ beliefs,
           const float* __restrict__ constraints,
           const float* __restrict__ fnembed,
           const float* __restrict__ mw1, const float* __restrict__ mb1,
           const float* __restrict__ mw2, const float* __restrict__ mb2,
           const float* __restrict__ uw1, const float* __restrict__ ub1,
           const float* __restrict__ uw2, const float* __restrict__ ub2,
           const float* __restrict__ gamma_, const float* __restrict__ beta_,
           float* __restrict__ out)
{
    extern __shared__ __align__(16) float sm[];
    const int tid = threadIdx.x;
    const int b  = blockIdx.z;
    const int x0 = blockIdx.x * TW;
    const int y0 = blockIdx.y * TH;

    // ================= Phase A: stage weights + inputs into smem =================
    // mw1 rows: [0,10)=W_self, [10,20)=W_neigh, [20,23)=W_con, [23,55)=W_fn
    for (int i = tid; i < 640; i += NTHREADS) {
        const int row = i >> 6, pos = i & 63;
        const int jj = (pos >> 1) + ((pos & 1) << 5);
        sm[OFF_WSELF  + i] = mw1[row * 64 + jj];
        sm[OFF_WNEIGH + i] = mw1[640 + row * 64 + jj];
        sm[OFF_MW2T + i] = mw2[jj * 10 + row];
        sm[OFF_UW2T + i] = uw2[jj * 10 + row];
    }
    for (int i = tid; i < 192; i += NTHREADS) {
        const int row = i >> 6, pos = i & 63;
        const int jj = (pos >> 1) + ((pos & 1) << 5);
        sm[OFF_WC + i] = mw1[1280 + row * 64 + jj];
    }
    if (tid < 64) {
        const int pos = 2 * (tid & 31) + (tid >> 5);   // pos(j=tid)
        sm[OFF_UB1 + pos] = ub1[tid];
        float s = mb1[tid];
        const float* f = fnembed + b * FD_;
        #pragma unroll
        for (int k = 0; k < FD_; ++k)
            s = fmaf(f[k], mw1[(23 + k) * HID_ + tid], s);
        sm[OFF_BASE + pos] = s;
    }
    if (tid >= 64 && tid < 74) {
        int k = tid - 64;
        sm[OFF_MB2   + k] = mb2[k];
        sm[OFF_UB2   + k] = ub2[k];
        sm[OFF_GAMMA + k] = gamma_[k];
        sm[OFF_BETA  + k] = beta_[k];
    }

    // beliefs halo (replicate-pad), rows padded to 12 floats
    for (int idx = tid; idx < NHALO * C_; idx += NTHREADS) {
        int p = idx / C_, i = idx - p * C_;
        int hr = p / HW, hc = p - hr * HW;
        int gy = min(max(y0 - 1 + hr, 0), H_ - 1);
        int gx = min(max(x0 - 1 + hc, 0), W_ - 1);
        sm[OFF_SB + p * 12 + i] = beliefs[((size_t)(b * H_ + gy) * W_ + gx) * C_ + i];
    }
    // constraints tile (float4, coalesced)
    {
        float4* dst = (float4*)&sm[OFF_SC];
        for (int idx = tid; idx < NPIX * 6; idx += NTHREADS) {
            int r = idx / (TW * 6), o = idx - r * (TW * 6);
            const float4* src = (const float4*)(constraints +
                ((size_t)(b * H_ + y0 + r) * W_ + x0) * 24);
            dst[idx] = src[o];
        }
    }
    __syncthreads();

    const int lane = tid & 31;
    const int wrp  = tid >> 5;   // 0..7
    const int pp   = 2 * lane;   // float2 offset for this thread's (j, j+32) pair

    // ================= Phase B: y = beliefs @ W_neigh over halo =================
    {
        float2 wn[C_];
        #pragma unroll
        for (int i = 0; i < C_; ++i) wn[i] = *(const float2*)&sm[OFF_WNEIGH + i * 64 + pp];
        #pragma unroll 2
        for (int hp = wrp; hp < NHALO; hp += NWARP) {
            const float4 s0 = *(const float4*)&sm[OFF_SB + hp * 12];
            const float4 s1 = *(const float4*)&sm[OFF_SB + hp * 12 + 4];
            const float2 s2 = *(const float2*)&sm[OFF_SB + hp * 12 + 8];
            float yx0 = 0.f, yx1 = 0.f, yy0 = 0.f, yy1 = 0.f;
            yx0 = fmaf(s0.x, wn[0].x, yx0); yy0 = fmaf(s0.x, wn[0].y, yy0);
            yx1 = fmaf(s0.y, wn[1].x, yx1); yy1 = fmaf(s0.y, wn[1].y, yy1);
            yx0 = fmaf(s0.z, wn[2].x, yx0); yy0 = fmaf(s0.z, wn[2].y, yy0);
            yx1 = fmaf(s0.w, wn[3].x, yx1); yy1 = fmaf(s0.w, wn[3].y, yy1);
            yx0 = fmaf(s1.x, wn[4].x, yx0); yy0 = fmaf(s1.x, wn[4].y, yy0);
            yx1 = fmaf(s1.y, wn[5].x, yx1); yy1 = fmaf(s1.y, wn[5].y, yy1);
            yx0 = fmaf(s1.z, wn[6].x, yx0); yy0 = fmaf(s1.z, wn[6].y, yy0);
            yx1 = fmaf(s1.w, wn[7].x, yx1); yy1 = fmaf(s1.w, wn[7].y, yy1);
            yx0 = fmaf(s2.x, wn[8].x, yx0); yy0 = fmaf(s2.x, wn[8].y, yy0);
            yx1 = fmaf(s2.y, wn[9].x, yx1); yy1 = fmaf(s2.y, wn[9].y, yy1);
            float2 y; y.x = yx0 + yx1; y.y = yy0 + yy1;
            *(float2*)&sm[OFF_SY + hp * HID_ + pp] = y;
        }
    }
    __syncthreads();

    // ================= Phase C: hs = sum_d relu(a + y_nb + c@wc), sliding window ==
    {
        float2 ws[C_];
        #pragma unroll
        for (int i = 0; i < C_; ++i) ws[i] = *(const float2*)&sm[OFF_WSELF + i * 64 + pp];
        const float2 wc0 = *(const float2*)&sm[OFF_WC + pp];
        const float2 wc1 = *(const float2*)&sm[OFF_WC + 64 + pp];
        const float2 wc2 = *(const float2*)&sm[OFF_WC + 128 + pp];
        const float2 bs  = *(const float2*)&sm[OFF_BASE + pp];

        const int row = wrp;                 // 0..7, one row of 16 px per warp
        const int rt = row * HW, rm = (row + 1) * HW, rb = (row + 2) * HW;

        // sliding 3x3 y-window (center slot 4 carried, unused)
        float2 yw[9];
        yw[0] = *(const float2*)&sm[OFF_SY + (rt + 0) * HID_ + pp];
        yw[1] = *(const float2*)&sm[OFF_SY + (rt + 1) * HID_ + pp];
        yw[3] = *(const float2*)&sm[OFF_SY + (rm + 0) * HID_ + pp];
        yw[4] = *(const float2*)&sm[OFF_SY + (rm + 1) * HID_ + pp];
        yw[6] = *(const float2*)&sm[OFF_SY + (rb + 0) * HID_ + pp];
        yw[7] = *(const float2*)&sm[OFF_SY + (rb + 1) * HID_ + pp];

        #pragma unroll 1
        for (int x = 0; x < TW; ++x) {
            yw[2] = *(const float2*)&sm[OFF_SY + (rt + x + 2) * HID_ + pp];
            yw[5] = *(const float2*)&sm[OFF_SY + (rm + x + 2) * HID_ + pp];
            yw[8] = *(const float2*)&sm[OFF_SY + (rb + x + 2) * HID_ + pp];

            const int p   = row * TW + x;
            const int hpc = rm + x + 1;

            // a = base + self @ W_self (uniform vec loads, 2 chains per half)
            const float4 s0 = *(const float4*)&sm[OFF_SB + hpc * 12];
            const float4 s1 = *(const float4*)&sm[OFF_SB + hpc * 12 + 4];
            const float2 s2 = *(const float2*)&sm[OFF_SB + hpc * 12 + 8];
            float ax0 = bs.x, ax1 = 0.f, ay0 = bs.y, ay1 = 0.f;
            ax0 = fmaf(s0.x, ws[0].x, ax0); ay0 = fmaf(s0.x, ws[0].y, ay0);
            ax1 = fmaf(s0.y, ws[1].x, ax1); ay1 = fmaf(s0.y, ws[1].y, ay1);
            ax0 = fmaf(s0.z, ws[2].x, ax0); ay0 = fmaf(s0.z, ws[2].y, ay0);
            ax1 = fmaf(s0.w, ws[3].x, ax1); ay1 = fmaf(s0.w, ws[3].y, ay1);
            ax0 = fmaf(s1.x, ws[4].x, ax0); ay0 = fmaf(s1.x, ws[4].y, ay0);
            ax1 = fmaf(s1.y, ws[5].x, ax1); ay1 = fmaf(s1.y, ws[5].y, ay1);
            ax0 = fmaf(s1.z, ws[6].x, ax0); ay0 = fmaf(s1.z, ws[6].y, ay0);
            ax1 = fmaf(s1.w, ws[7].x, ax1); ay1 = fmaf(s1.w, ws[7].y, ay1);
            ax0 = fmaf(s2.x, ws[8].x, ax0); ay0 = fmaf(s2.x, ws[8].y, ay0);
            ax1 = fmaf(s2.y, ws[9].x, ax1); ay1 = fmaf(s2.y, ws[9].y, ay1);
            const float ax = ax0 + ax1, ay = ay0 + ay1;

            // constraints (uniform vec loads, issued once per warp)
            float cc[24];
            #pragma unroll
            for (int q = 0; q < 6; ++q) {
                const float4 v = *(const float4*)&sm[OFF_SC + p * 24 + q * 4];
                cc[q*4+0] = v.x; cc[q*4+1] = v.y; cc[q*4+2] = v.z; cc[q*4+3] = v.w;
            }

            const int DI[8] = {0,1,2,3,5,6,7,8};
            float mx[8], my[8];
            #pragma unroll
            for (int d = 0; d < 8; ++d) {
                const float2 yn = yw[DI[d]];
                float tx = ax + yn.x;
                float ty = ay + yn.y;
                tx = fmaf(cc[3*d+0], wc0.x, tx); ty = fmaf(cc[3*d+0], wc0.y, ty);
                tx = fmaf(cc[3*d+1], wc1.x, tx); ty = fmaf(cc[3*d+1], wc1.y, ty);
                tx = fmaf(cc[3*d+2], wc2.x, tx); ty = fmaf(cc[3*d+2], wc2.y, ty);
                mx[d] = fmaxf(tx, 0.f);
                my[d] = fmaxf(ty, 0.f);
            }
            float2 hs;
            hs.x = ((mx[0]+mx[1]) + (mx[2]+mx[3])) + ((mx[4]+mx[5]) + (mx[6]+mx[7]));
            hs.y = ((my[0]+my[1]) + (my[2]+my[3])) + ((my[4]+my[5]) + (my[6]+my[7]));
            *(float2*)&sm[OFF_SHS + p * HID_ + pp] = hs;

            yw[0]=yw[1]; yw[1]=yw[2];
            yw[3]=yw[4]; yw[4]=yw[5];
            yw[6]=yw[7]; yw[7]=yw[8];
        }
    }
    __syncthreads();

    // 8-lane-group mapping for phases D and F (pos-order)
    const int g    = lane >> 3;
    const int li   = lane & 7;
    const int j0   = li << 3;

    // ================= Phase D: agg = (mean_d relu)@mw2 + mb2  (+ stage uw1) =====
    {
        // stage uw1 (pos-interleaved) into the dead upper half of SC — used in E
        for (int i = tid; i < 1280; i += NTHREADS) {
            const int row = i >> 6, pos = i & 63;
            const int jj = (pos >> 1) + ((pos & 1) << 5);
            sm[OFF_UW1X + i] = uw1[row * 64 + jj];
        }

        float w2[10][8];   // register-resident across all passes
        #pragma unroll
        for (int k = 0; k < 10; ++k) {
            *(float4*)&w2[k][0] = *(const float4*)&sm[OFF_MW2T + k * 64 + j0];
            *(float4*)&w2[k][4] = *(const float4*)&sm[OFF_MW2T + k * 64 + j0 + 4];
        }
        float mb2r[10];
        #pragma unroll
        for (int k = 0; k < 10; ++k) mb2r[k] = sm[OFF_MB2 + k];

        #pragma unroll 1
        for (int pass = 0; pass < 4; ++pass) {
            const int p = pass * 32 + wrp * 4 + g;
            float hs[8];
            *(float4*)&hs[0] = *(const float4*)&sm[OFF_SHS + p * 64 + j0];
            *(float4*)&hs[4] = *(const float4*)&sm[OFF_SHS + p * 64 + j0 + 4];
            float agg[10];
            #pragma unroll
            for (int k = 0; k < 10; ++k) {
                float s0 = 0.f, s1 = 0.f;
                #pragma unroll
                for (int jj = 0; jj < 4; ++jj) {
                    s0 = fmaf(hs[jj],     w2[k][jj],     s0);
                    s1 = fmaf(hs[jj + 4], w2[k][jj + 4], s1);
                }
                agg[k] = s0 + s1;
            }
            #pragma unroll
            for (int o = 1; o < 8; o <<= 1) {
                #pragma unroll
                for (int k = 0; k < 10; ++k)
                    agg[k] += __shfl_xor_sync(0xffffffffu, agg[k], o);
            }
            if (li == 0) {
                #pragma unroll
                for (int k = 0; k < 10; k += 2) {
                    float2 v; v.x = fmaf(agg[k],   0.125f, mb2r[k]);
                              v.y = fmaf(agg[k+1], 0.125f, mb2r[k+1]);
                    *(float2*)&sm[OFF_SAGG + p * 12 + k] = v;
                }
            }
        }
    }
    __syncthreads();

    // ================= Phase E: u = relu([self,agg] @ uw1 + ub1) =================
    {
        float2 w1[20];     // uw1[:, pair] register-resident (40 regs)
        #pragma unroll
        for (int i = 0; i < 20; ++i) w1[i] = *(const float2*)&sm[OFF_UW1X + i * 64 + pp];
        const float2 b1 = *(const float2*)&sm[OFF_UB1 + pp];

        #pragma unroll 2
        for (int p = wrp; p < NPIX; p += NWARP) {
            const int hpc = (p / TW + 1) * HW + (p % TW) + 1;
            const float4 s0 = *(const float4*)&sm[OFF_SB + hpc * 12];
            const float4 s1 = *(const float4*)&sm[OFF_SB + hpc * 12 + 4];
            const float2 s2 = *(const float2*)&sm[OFF_SB + hpc * 12 + 8];
            const float4 a0 = *(const float4*)&sm[OFF_SAGG + p * 12];
            const float4 a1 = *(const float4*)&sm[OFF_SAGG + p * 12 + 4];
            const float2 a2 = *(const float2*)&sm[OFF_SAGG + p * 12 + 8];
            float ux0 = b1.x, ux1 = 0.f, uy0 = b1.y, uy1 = 0.f;
            ux0 = fmaf(s0.x, w1[0].x,  ux0); uy0 = fmaf(s0.x, w1[0].y,  uy0);
            ux1 = fmaf(s0.y, w1[1].x,  ux1); uy1 = fmaf(s0.y, w1[1].y,  uy1);
            ux0 = fmaf(s0.z, w1[2].x,  ux0); uy0 = fmaf(s0.z, w1[2].y,  uy0);
            ux1 = fmaf(s0.w, w1[3].x,  ux1); uy1 = fmaf(s0.w, w1[3].y,  uy1);
            ux0 = fmaf(s1.x, w1[4].x,  ux0); uy0 = fmaf(s1.x, w1[4].y,  uy0);
            ux1 = fmaf(s1.y, w1[5].x,  ux1); uy1 = fmaf(s1.y, w1[5].y,  uy1);
            ux0 = fmaf(s1.z, w1[6].x,  ux0); uy0 = fmaf(s1.z, w1[6].y,  uy0);
            ux1 = fmaf(s1.w, w1[7].x,  ux1); uy1 = fmaf(s1.w, w1[7].y,  uy1);
            ux0 = fmaf(s2.x, w1[8].x,  ux0); uy0 = fmaf(s2.x, w1[8].y,  uy0);
            ux1 = fmaf(s2.y, w1[9].x,  ux1); uy1 = fmaf(s2.y, w1[9].y,  uy1);
            ux0 = fmaf(a0.x, w1[10].x, ux0); uy0 = fmaf(a0.x, w1[10].y, uy0);
            ux1 = fmaf(a0.y, w1[11].x, ux1); uy1 = fmaf(a0.y, w1[11].y, uy1);
            ux0 = fmaf(a0.z, w1[12].x, ux0); uy0 = fmaf(a0.z, w1[12].y, uy0);
            ux1 = fmaf(a0.w, w1[13].x, ux1); uy1 = fmaf(a0.w, w1[13].y, uy1);
            ux0 = fmaf(a1.x, w1[14].x, ux0); uy0 = fmaf(a1.x, w1[14].y, uy0);
            ux1 = fmaf(a1.y, w1[15].x, ux1); uy1 = fmaf(a1.y, w1[15].y, uy1);
            ux0 = fmaf(a1.z, w1[16].x, ux0); uy0 = fmaf(a1.z, w1[16].y, uy0);
            ux1 = fmaf(a1.w, w1[17].x, ux1); uy1 = fmaf(a1.w, w1[17].y, uy1);
            ux0 = fmaf(a2.x, w1[18].x, ux0); uy0 = fmaf(a2.x, w1[18].y, uy0);
            ux1 = fmaf(a2.y, w1[19].x, ux1); uy1 = fmaf(a2.y, w1[19].y, uy1);
            float2 u; u.x = fmaxf(ux0 + ux1, 0.f); u.y = fmaxf(uy0 + uy1, 0.f);
            *(float2*)&sm[OFF_SU + p * 64 + pp] = u;
        }
    }
    __syncthreads();

    // ================= Phase F: upd = u @ uw2 + ub2 ; residual + LN =================
    {
        float w2[10][8];   // uw2t register-resident
        #pragma unroll
        for (int k = 0; k < 10; ++k) {
            *(float4*)&w2[k][0] = *(const float4*)&sm[OFF_UW2T + k * 64 + j0];
            *(float4*)&w2[k][4] = *(const float4*)&sm[OFF_UW2T + k * 64 + j0 + 4];
        }

        #pragma unroll 1
        for (int pass = 0; pass < 4; ++pass) {
            const int p = pass * 32 + wrp * 4 + g;
            float u[8];
            *(float4*)&u[0] = *(const float4*)&sm[OFF_SU + p * 64 + j0];
            *(float4*)&u[4] = *(const float4*)&sm[OFF_SU + p * 64 + j0 + 4];
            float upd[10];
            #pragma unroll
            for (int k = 0; k < 10; ++k) {
                float s0 = 0.f, s1 = 0.f;
                #pragma unroll
                for (int jj = 0; jj < 4; ++jj) {
                    s0 = fmaf(u[jj],     w2[k][jj],     s0);
                    s1 = fmaf(u[jj + 4], w2[k][jj + 4], s1);
                }
                upd[k] = s0 + s1;
            }
            #pragma unroll
            for (int o = 1; o < 8; o <<= 1) {
                #pragma unroll
                for (int k = 0; k < 10; ++k)
                    upd[k] += __shfl_xor_sync(0xffffffffu, upd[k], o);
            }
            if (li == 0) {
                const int hpc = (p / TW + 1) * HW + (p % TW) + 1;
                const float4 s0 = *(const float4*)&sm[OFF_SB + hpc * 12];
                const float4 s1 = *(const float4*)&sm[OFF_SB + hpc * 12 + 4];
                const float2 s2 = *(const float2*)&sm[OFF_SB + hpc * 12 + 8];
                float sf[10] = {s0.x,s0.y,s0.z,s0.w,s1.x,s1.y,s1.z,s1.w,s2.x,s2.y};
                float x[10]; float mu = 0.f;
                #pragma unroll
                for (int k = 0; k < 10; ++k) {
                    float xv = fmaf(0.5f, upd[k] + sm[OFF_UB2 + k], sf[k]);
                    x[k] = xv; mu += xv;
                }
                mu *= 0.1f;
                float var = 0.f;
                #pragma unroll
                for (int k = 0; k < 10; ++k) { float dk = x[k] - mu; var = fmaf(dk, dk, var); }
                const float inv = rsqrtf(var * 0.1f + 1e-5f);
                #pragma unroll
                for (int k = 0; k < 10; k += 2) {
                    float2 v;
                    v.x = fmaf((x[k]   - mu) * inv, sm[OFF_GAMMA + k],   sm[OFF_BETA + k]);
                    v.y = fmaf((x[k+1] - mu) * inv, sm[OFF_GAMMA + k+1], sm[OFF_BETA + k+1]);
                    *(float2*)&sm[OFF_SOUT + p * C_ + k] = v;
                }
            }
        }
    }
    __syncthreads();

    // ================= Phase G: coalesced float4 store =================
    {
        const float4* src = (const float4*)&sm[OFF_SOUT];
        for (int idx = tid; idx < NPIX * C_ / 4; idx += NTHREADS) {
            int r = idx / (TW * C_ / 4), o = idx - r * (TW * C_ / 4);
            float4* dst = (float4*)(out + ((size_t)(b * H_ + y0 + r) * W_ + x0) * C_);
            dst[o] = src[idx];
        }
    }
}

extern "C" void kernel_launch(void* const* d_in, const int* in_sizes, int n_in,
                              void* d_out, int out_size)
{
    const float* beliefs     = (const float*)d_in[0];
    const float* constraints = (const float*)d_in[1];
    const float* fnembed     = (const float*)d_in[2];
    const float* mw1         = (const float*)d_in[3];
    const float* mb1         = (const float*)d_in[4];
    const float* mw2         = (const float*)d_in[5];
    const float* mb2         = (const float*)d_in[6];
    const float* uw1         = (const float*)d_in[7];
    const float* ub1         = (const float*)d_in[8];
    const float* uw2         = (const float*)d_in[9];
    const float* ub2         = (const float*)d_in[10];
    const float* gamma_      = (const float*)d_in[11];
    const float* beta_       = (const float*)d_in[12];
    float* out = (float*)d_out;

    cudaFuncSetAttribute(cmp_kernel, cudaFuncAttributeMaxDynamicSharedMemorySize, SMEM_BYTES);

    dim3 grid(W_ / TW, H_ / TH, B_);
    cmp_kernel<<<grid, NTHREADS, SMEM_BYTES>>>(
        beliefs, constraints, fnembed, mw1, mb1, mw2, mb2,
        uw1, ub1, uw2, ub2, gamma_, beta_, out);
}